// round 8
// baseline (speedup 1.0000x reference)
#include <cuda_runtime.h>
#include <cuda_bf16.h>
#include <cstdint>
#include <math.h>

#define NB 2
#define NT 2048
#define NC 1024
#define NH 16
#define DH 64
#define NM (NB*NT)   // 4096 rows

// ---------------------------------------------------------------------------
// Scratch (__device__ globals; no allocations)
// ---------------------------------------------------------------------------
__device__ float g_Q[(size_t)NM*NC];
__device__ float g_K[(size_t)NM*NC];
__device__ float g_V[(size_t)NM*NC];
__device__ float g_Y[(size_t)NM*NC];
__device__ unsigned short g_Ahi[(size_t)NM*NC];          // bf16 raw
__device__ unsigned short g_Alo[(size_t)NM*NC];
__device__ unsigned short g_Wthi[(size_t)4*NC*NC];       // W^T [N,K] bf16 hi
__device__ unsigned short g_Wtlo[(size_t)4*NC*NC];       // W^T [N,K] bf16 lo
__device__ int g_badQ;   // bf16 mma arm failed
__device__ int g_badV;   // tf32 mma arm failed

// ---------------------------------------------------------------------------
// Helpers
// ---------------------------------------------------------------------------
__device__ __forceinline__ void mma_bf16(float* d, const uint32_t* a, const uint32_t* b) {
    asm volatile("mma.sync.aligned.m16n8k16.row.col.f32.bf16.bf16.f32 "
        "{%0,%1,%2,%3}, {%4,%5,%6,%7}, {%8,%9}, {%0,%1,%2,%3};"
        : "+f"(d[0]), "+f"(d[1]), "+f"(d[2]), "+f"(d[3])
        : "r"(a[0]), "r"(a[1]), "r"(a[2]), "r"(a[3]), "r"(b[0]), "r"(b[1]));
}
__device__ __forceinline__ void mma_tf32(float* d, const uint32_t* a, const uint32_t* b) {
    asm volatile("mma.sync.aligned.m16n8k8.row.col.f32.tf32.tf32.f32 "
        "{%0,%1,%2,%3}, {%4,%5,%6,%7}, {%8,%9}, {%0,%1,%2,%3};"
        : "+f"(d[0]), "+f"(d[1]), "+f"(d[2]), "+f"(d[3])
        : "r"(a[0]), "r"(a[1]), "r"(a[2]), "r"(a[3]), "r"(b[0]), "r"(b[1]));
}
__device__ __forceinline__ void bsplit(float x, unsigned short& h, unsigned short& l) {
    __nv_bfloat16 bh = __float2bfloat16(x);
    float fh = __bfloat162float(bh);
    __nv_bfloat16 bl = __float2bfloat16(x - fh);
    h = __bfloat16_as_ushort(bh);
    l = __bfloat16_as_ushort(bl);
}
// tf32 split: hi = x with low 13 mantissa bits cleared (exact tf32), lo = x - hi
__device__ __forceinline__ void tsplit(float x, uint32_t& h, uint32_t& l) {
    uint32_t hb = __float_as_uint(x) & 0xFFFFE000u;
    h = hb;
    l = __float_as_uint(x - __uint_as_float(hb));
}

// ---------------------------------------------------------------------------
__global__ void zero_flag_kernel() { g_badQ = 0; g_badV = 0; }

// ---------------------------------------------------------------------------
// fp32 -> (hi, lo) bf16 split. gated=1: run only if bf16 arm verified.
// ---------------------------------------------------------------------------
__global__ __launch_bounds__(256)
void convert_split_kernel(const float* __restrict__ in,
                          unsigned short* __restrict__ hi,
                          unsigned short* __restrict__ lo, int gated)
{
    if (gated && g_badQ != 0) return;
    int i = blockIdx.x * blockDim.x + threadIdx.x;
    float4 v = ((const float4*)in)[i];
    ushort4 h, l;
    bsplit(v.x, h.x, l.x);
    bsplit(v.y, h.y, l.y);
    bsplit(v.z, h.z, l.z);
    bsplit(v.w, h.w, l.w);
    ((ushort4*)hi)[i] = h;
    ((ushort4*)lo)[i] = l;
}

// ---------------------------------------------------------------------------
// Weight transpose + split: W[K,N] fp32 -> Wt_hi/lo[N,K] bf16 (z = 0..3)
// ---------------------------------------------------------------------------
__global__ __launch_bounds__(256)
void wsplit_kernel(const float* __restrict__ Wq, const float* __restrict__ Wk,
                   const float* __restrict__ Wv, const float* __restrict__ Wo)
{
    __shared__ float t[32][33];
    int z = blockIdx.z;
    const float* W = (z == 0) ? Wq : (z == 1) ? Wk : (z == 2) ? Wv : Wo;
    int n0 = blockIdx.x * 32, k0 = blockIdx.y * 32;
    int tx = threadIdx.x, ty = threadIdx.y;
#pragma unroll
    for (int j = 0; j < 4; j++)
        t[ty + j * 8][tx] = W[(size_t)(k0 + ty + j * 8) * NC + n0 + tx];
    __syncthreads();
#pragma unroll
    for (int j = 0; j < 4; j++) {
        int r = ty + j * 8;
        float v = t[tx][r];
        size_t off = (size_t)z * NC * NC + (size_t)(n0 + r) * NC + k0 + tx;
        bsplit(v, g_Wthi[off], g_Wtlo[off]);
    }
}

// ---------------------------------------------------------------------------
// ARM 1: bf16 mma GEMM, fragments loaded DIRECTLY FROM GLOBAL (no smem).
// Warp computes 16 rows x 64 cols. Block 256 thr = 8 warps -> 128 rows.
// mode 0: z = blockIdx.z in {0 -> g_Q, 1 -> g_K}, A = x-split
// mode 1: z = 3 (Wo), C = Cext, A = Y-split.  gate=1: need g_badQ == 0.
// ---------------------------------------------------------------------------
__global__ __launch_bounds__(256)
void mma_qk_kernel(const float* __restrict__ bq, const float* __restrict__ bk,
                   const float* __restrict__ bo, float* __restrict__ Cext,
                   int mode, int gate)
{
    if (gate && g_badQ != 0) return;
    int tid = threadIdx.x, w = tid >> 5, lane = tid & 31;
    int g8 = lane >> 2, t4 = lane & 3;
    int n0 = blockIdx.x * 64, m0 = blockIdx.y * 128;
    int z = (mode == 0) ? blockIdx.z : 3;
    const float* bias = (mode == 0) ? ((z == 0) ? bq : bk) : bo;
    float* C = (mode == 0) ? ((z == 0) ? g_Q : g_K) : Cext;

    int mrow = m0 + w * 16 + g8;
    const unsigned short* Ah = g_Ahi + (size_t)mrow * NC + 2 * t4;
    const unsigned short* Al = g_Alo + (size_t)mrow * NC + 2 * t4;
    const unsigned short* Bh = g_Wthi + (size_t)z * NC * NC + 2 * t4;
    const unsigned short* Bl = g_Wtlo + (size_t)z * NC * NC + 2 * t4;

    float acc[8][4];
#pragma unroll
    for (int nf = 0; nf < 8; nf++)
#pragma unroll
        for (int q = 0; q < 4; q++) acc[nf][q] = 0.0f;

    for (int kk = 0; kk < NC; kk += 16) {
        uint32_t ah[4], al[4];
        ah[0] = *(const uint32_t*)(Ah + kk);
        ah[1] = *(const uint32_t*)(Ah + 8 * NC + kk);
        ah[2] = *(const uint32_t*)(Ah + kk + 8);
        ah[3] = *(const uint32_t*)(Ah + 8 * NC + kk + 8);
        al[0] = *(const uint32_t*)(Al + kk);
        al[1] = *(const uint32_t*)(Al + 8 * NC + kk);
        al[2] = *(const uint32_t*)(Al + kk + 8);
        al[3] = *(const uint32_t*)(Al + 8 * NC + kk + 8);
#pragma unroll
        for (int nf = 0; nf < 8; nf++) {
            size_t boff = (size_t)(n0 + nf * 8 + g8) * NC + kk;
            uint32_t bh[2], bl[2];
            bh[0] = *(const uint32_t*)(Bh + boff);
            bh[1] = *(const uint32_t*)(Bh + boff + 8);
            bl[0] = *(const uint32_t*)(Bl + boff);
            bl[1] = *(const uint32_t*)(Bl + boff + 8);
            mma_bf16(acc[nf], ah, bh);
            mma_bf16(acc[nf], al, bh);
            mma_bf16(acc[nf], ah, bl);
        }
    }

#pragma unroll
    for (int nf = 0; nf < 8; nf++) {
        int col = n0 + nf * 8 + t4 * 2;
        float2 b2 = *(const float2*)(bias + col);
        float2 o;
        o.x = acc[nf][0] + b2.x; o.y = acc[nf][1] + b2.y;
        *(float2*)(C + (size_t)mrow * NC + col) = o;
        o.x = acc[nf][2] + b2.x; o.y = acc[nf][3] + b2.y;
        *(float2*)(C + (size_t)(mrow + 8) * NC + col) = o;
    }
}

// ---------------------------------------------------------------------------
// ARM 2: tf32 mma GEMM for V = x @ Wv + bv, on-the-fly hi/lo split,
// all operands straight from the fp32 inputs (no prep kernels at all).
// ---------------------------------------------------------------------------
__global__ __launch_bounds__(256)
void tf32_v_kernel(const float* __restrict__ x, const float* __restrict__ Wv,
                   const float* __restrict__ bv)
{
    int tid = threadIdx.x, w = tid >> 5, lane = tid & 31;
    int g8 = lane >> 2, t4 = lane & 3;
    int n0 = blockIdx.x * 64, m0 = blockIdx.y * 128;
    int mrow = m0 + w * 16 + g8;
    const float* Ar = x + (size_t)mrow * NC + t4;

    float acc[8][4];
#pragma unroll
    for (int nf = 0; nf < 8; nf++)
#pragma unroll
        for (int q = 0; q < 4; q++) acc[nf][q] = 0.0f;

    for (int kk = 0; kk < NC; kk += 8) {
        uint32_t ah[4], al[4];
        tsplit(Ar[kk],              ah[0], al[0]);
        tsplit(Ar[8 * NC + kk],     ah[1], al[1]);
        tsplit(Ar[kk + 4],          ah[2], al[2]);
        tsplit(Ar[8 * NC + kk + 4], ah[3], al[3]);
#pragma unroll
        for (int nf = 0; nf < 8; nf++) {
            int ncol = n0 + nf * 8 + g8;
            uint32_t bh[2], bl[2];
            tsplit(Wv[(size_t)(kk + t4) * NC + ncol],     bh[0], bl[0]);
            tsplit(Wv[(size_t)(kk + t4 + 4) * NC + ncol], bh[1], bl[1]);
            mma_tf32(acc[nf], ah, bh);
            mma_tf32(acc[nf], ah, bl);
            mma_tf32(acc[nf], al, bh);
        }
    }

#pragma unroll
    for (int nf = 0; nf < 8; nf++) {
        int col = n0 + nf * 8 + t4 * 2;
        float2 b2 = *(const float2*)(bv + col);
        float2 o;
        o.x = acc[nf][0] + b2.x; o.y = acc[nf][1] + b2.y;
        *(float2*)(g_V + (size_t)mrow * NC + col) = o;
        o.x = acc[nf][2] + b2.x; o.y = acc[nf][3] + b2.y;
        *(float2*)(g_V + (size_t)(mrow + 8) * NC + col) = o;
    }
}

// ---------------------------------------------------------------------------
// Device-side checks: recompute a 128x128 tile in fp32, flag on mismatch.
// which=0: check g_Q vs x@Wq+bq -> g_badQ;  which=1: g_V vs x@Wv+bv -> g_badV
// ---------------------------------------------------------------------------
__global__ __launch_bounds__(256)
void ref_check_kernel(const float* __restrict__ x, const float* __restrict__ W,
                      const float* __restrict__ b, int which)
{
    int idx = blockIdx.x * 256 + threadIdx.x;   // 0..16383
    int r = idx >> 7, c = idx & 127;
    const float* xr = x + (size_t)r * NC;
    float s = 0.0f;
#pragma unroll 4
    for (int k = 0; k < NC; k++)
        s += xr[k] * W[(size_t)k * NC + c];
    s += b[c];
    const float* Cq = which ? g_V : g_Q;
    float q = Cq[(size_t)r * NC + c];
    if (fabsf(q - s) > 0.02f * (fabsf(s) + 0.5f)) {
        if (which) atomicExch(&g_badV, 1);
        else       atomicExch(&g_badQ, 1);
    }
}

// ---------------------------------------------------------------------------
// Proven R1 fp32 SGEMM fallback, per-matrix gated.
// mode 0: z in {0,1,2} -> g_Q/g_K/g_V (z<2 gated on g_badQ, z==2 on g_badV)
// mode 1: out-proj, gated on g_badQ
// ---------------------------------------------------------------------------
#define GBM 128
#define GBN 128
#define GBK 8

__global__ __launch_bounds__(256)
void sgemm_bias_kernel(const float* __restrict__ Aext,
                       const float* __restrict__ W0, const float* __restrict__ W1,
                       const float* __restrict__ W2,
                       const float* __restrict__ b0, const float* __restrict__ b1,
                       const float* __restrict__ b2,
                       float* __restrict__ Cext, int mode)
{
    int z = blockIdx.z;
    if (mode == 0) {
        if (z == 2) { if (g_badV == 0) return; }
        else        { if (g_badQ == 0) return; }
    } else {
        if (g_badQ == 0) return;
    }

    const int N = NC, K = NC;
    const float* A; const float* W; const float* bias; float* C;
    if (mode == 0) {
        A = Aext;
        W    = (z == 0) ? W0 : (z == 1) ? W1 : W2;
        bias = (z == 0) ? b0 : (z == 1) ? b1 : b2;
        C    = (z == 0) ? g_Q : (z == 1) ? g_K : g_V;
    } else {
        A = g_Y; W = W0; bias = b0; C = Cext;
    }

    __shared__ float As[GBK][GBM];
    __shared__ float Bs[GBK][GBN];

    int tid = threadIdx.x;
    int bx = blockIdx.x, by = blockIdx.y;

    float acc[8][8];
#pragma unroll
    for (int i = 0; i < 8; i++)
#pragma unroll
        for (int j = 0; j < 8; j++) acc[i][j] = 0.0f;

    const float* Ab = A + (size_t)by * GBM * K;
    const float* Wb = W + (size_t)bx * GBN;

    int arow = tid >> 1, acol = (tid & 1) * 4;
    int brow = tid >> 5, bcol = (tid & 31) * 4;
    int rg = (tid >> 4) * 8;
    int cg = (tid & 15) * 8;

    for (int kt = 0; kt < K; kt += GBK) {
        float4 av = *(const float4*)(Ab + (size_t)arow * K + kt + acol);
        float4 bv = *(const float4*)(Wb + (size_t)(kt + brow) * N + bcol);
        __syncthreads();
        As[acol + 0][arow] = av.x;
        As[acol + 1][arow] = av.y;
        As[acol + 2][arow] = av.z;
        As[acol + 3][arow] = av.w;
        *(float4*)&Bs[brow][bcol] = bv;
        __syncthreads();
#pragma unroll
        for (int k = 0; k < GBK; k++) {
            float ra[8], rb[8];
            *(float4*)&ra[0] = *(const float4*)&As[k][rg];
            *(float4*)&ra[4] = *(const float4*)&As[k][rg + 4];
            *(float4*)&rb[0] = *(const float4*)&Bs[k][cg];
            *(float4*)&rb[4] = *(const float4*)&Bs[k][cg + 4];
#pragma unroll
            for (int i = 0; i < 8; i++)
#pragma unroll
                for (int j = 0; j < 8; j++)
                    acc[i][j] += ra[i] * rb[j];
        }
    }

    size_t row0 = (size_t)by * GBM + rg;
    int col0 = bx * GBN + cg;
#pragma unroll
    for (int i = 0; i < 8; i++) {
#pragma unroll
        for (int j = 0; j < 8; j += 4) {
            float4 o;
            o.x = acc[i][j + 0] + bias[col0 + j + 0];
            o.y = acc[i][j + 1] + bias[col0 + j + 1];
            o.z = acc[i][j + 2] + bias[col0 + j + 2];
            o.w = acc[i][j + 3] + bias[col0 + j + 3];
            *(float4*)(C + (row0 + i) * N + col0 + j) = o;
        }
    }
}

// ---------------------------------------------------------------------------
// Flash attention (proven R1 version)
// ---------------------------------------------------------------------------
#define FBQ 64
#define FBK 32
#define QP 65
#define KP 66
#define SP 33

__global__ __launch_bounds__(128)
void flash_kernel()
{
    __shared__ float Qs[FBQ][QP];
    __shared__ float KS[2112];
    __shared__ float Vs[FBK][DH];

    int tid = threadIdx.x;
    int qt = blockIdx.x;
    int bh = blockIdx.y;
    int b = bh >> 4, h = bh & 15;

    const float* Qg = g_Q + (size_t)b * NT * NC + h * DH;
    const float* Kg = g_K + (size_t)b * NT * NC + h * DH;
    const float* Vg = g_V + (size_t)b * NT * NC + h * DH;

    int ty = tid >> 3;
    int tx = tid & 7;
    int ty4 = ty * 4;

    {
        int lq = tid >> 4;
        int d  = (tid & 15) * 4;
#pragma unroll
        for (int r = 0; r < 8; r++) {
            int q = lq + r * 8;
            float4 v = *(const float4*)(Qg + (size_t)(qt * FBQ + q) * NC + d);
            Qs[q][d + 0] = v.x * 0.125f;
            Qs[q][d + 1] = v.y * 0.125f;
            Qs[q][d + 2] = v.z * 0.125f;
            Qs[q][d + 3] = v.w * 0.125f;
        }
    }

    float oa[4][8];
    float m_r[4], l_r[4];
#pragma unroll
    for (int i = 0; i < 4; i++) {
        m_r[i] = -1e30f; l_r[i] = 0.0f;
#pragma unroll
        for (int c = 0; c < 8; c++) oa[i][c] = 0.0f;
    }

    for (int kt = 0; kt < NT / FBK; kt++) {
        const float* Kt = Kg + (size_t)(kt * FBK) * NC;
        const float* Vt = Vg + (size_t)(kt * FBK) * NC;

        __syncthreads();
        {
            int lk = tid >> 4;
            int d  = (tid & 15) * 4;
#pragma unroll
            for (int r = 0; r < 4; r++) {
                int key = lk + r * 8;
                float4 kv = *(const float4*)(Kt + (size_t)key * NC + d);
                float* Kp = &KS[key * KP + d];
                Kp[0] = kv.x; Kp[1] = kv.y; Kp[2] = kv.z; Kp[3] = kv.w;
                float4 vv = *(const float4*)(Vt + (size_t)key * NC + d);
                *(float4*)&Vs[key][d] = vv;
            }
        }
        __syncthreads();

        float s[4][4];
#pragma unroll
        for (int i = 0; i < 4; i++)
#pragma unroll
            for (int j = 0; j < 4; j++) s[i][j] = 0.0f;

#pragma unroll 4
        for (int d = 0; d < DH; d++) {
            float rq[4], rk[4];
#pragma unroll
            for (int i = 0; i < 4; i++) rq[i] = Qs[ty4 + i][d];
#pragma unroll
            for (int j = 0; j < 4; j++) rk[j] = KS[(tx + 8 * j) * KP + d];
#pragma unroll
            for (int i = 0; i < 4; i++)
#pragma unroll
                for (int j = 0; j < 4; j++)
                    s[i][j] += rq[i] * rk[j];
        }
        __syncthreads();

        float p[4][4], corr[4], rsum[4];
#pragma unroll
        for (int i = 0; i < 4; i++) {
            float tm = fmaxf(fmaxf(s[i][0], s[i][1]), fmaxf(s[i][2], s[i][3]));
            tm = fmaxf(tm, __shfl_xor_sync(0xffffffffu, tm, 1));
            tm = fmaxf(tm, __shfl_xor_sync(0xffffffffu, tm, 2));
            tm = fmaxf(tm, __shfl_xor_sync(0xffffffffu, tm, 4));
            float mnew = fmaxf(m_r[i], tm);
            corr[i] = __expf(m_r[i] - mnew);
            float rs = 0.0f;
#pragma unroll
            for (int j = 0; j < 4; j++) {
                p[i][j] = __expf(s[i][j] - mnew);
                rs += p[i][j];
            }
            rs += __shfl_xor_sync(0xffffffffu, rs, 1);
            rs += __shfl_xor_sync(0xffffffffu, rs, 2);
            rs += __shfl_xor_sync(0xffffffffu, rs, 4);
            rsum[i] = rs;
            m_r[i] = mnew;
        }
#pragma unroll
        for (int i = 0; i < 4; i++) {
            l_r[i] = l_r[i] * corr[i] + rsum[i];
#pragma unroll
            for (int c = 0; c < 8; c++) oa[i][c] *= corr[i];
        }

#pragma unroll
        for (int i = 0; i < 4; i++)
#pragma unroll
            for (int j = 0; j < 4; j++)
                KS[(ty4 + i) * SP + (tx + 8 * j)] = p[i][j];
        __syncthreads();

#pragma unroll 4
        for (int k = 0; k < FBK; k++) {
            float rs[4];
#pragma unroll
            for (int i = 0; i < 4; i++) rs[i] = KS[(ty4 + i) * SP + k];
            float4 v0 = *(const float4*)&Vs[k][tx * 8];
            float4 v1 = *(const float4*)&Vs[k][tx * 8 + 4];
#pragma unroll
            for (int i = 0; i < 4; i++) {
                oa[i][0] += rs[i] * v0.x;
                oa[i][1] += rs[i] * v0.y;
                oa[i][2] += rs[i] * v0.z;
                oa[i][3] += rs[i] * v0.w;
                oa[i][4] += rs[i] * v1.x;
                oa[i][5] += rs[i] * v1.y;
                oa[i][6] += rs[i] * v1.z;
                oa[i][7] += rs[i] * v1.w;
            }
        }
    }

#pragma unroll
    for (int i = 0; i < 4; i++) {
        float inv = 1.0f / l_r[i];
        size_t row = (size_t)b * NT + qt * FBQ + ty4 + i;
        float* Yp = g_Y + row * NC + h * DH + tx * 8;
        float4 o0, o1;
        o0.x = oa[i][0] * inv; o0.y = oa[i][1] * inv;
        o0.z = oa[i][2] * inv; o0.w = oa[i][3] * inv;
        o1.x = oa[i][4] * inv; o1.y = oa[i][5] * inv;
        o1.z = oa[i][6] * inv; o1.w = oa[i][7] * inv;
        *(float4*)Yp = o0;
        *(float4*)(Yp + 4) = o1;
    }
}

// ---------------------------------------------------------------------------
extern "C" void kernel_launch(void* const* d_in, const int* in_sizes, int n_in,
                              void* d_out, int out_size)
{
    const float* x  = (const float*)d_in[0];
    const float* Wq = (const float*)d_in[1];
    const float* bq = (const float*)d_in[2];
    const float* Wk = (const float*)d_in[3];
    const float* bk = (const float*)d_in[4];
    const float* Wv = (const float*)d_in[5];
    const float* bv = (const float*)d_in[6];
    const float* Wo = (const float*)d_in[7];
    const float* bo = (const float*)d_in[8];
    float* out = (float*)d_out;

    // 0) reset flags
    zero_flag_kernel<<<1, 1>>>();
    // 1) bf16 splits (x + all weights)
    convert_split_kernel<<<(NM * NC) / 1024, 256>>>(x, g_Ahi, g_Alo, 0);
    wsplit_kernel<<<dim3(NC / 32, NC / 32, 4), dim3(32, 8)>>>(Wq, Wk, Wv, Wo);
    // 2) ARM 1: Q, K via bf16 mma (global-direct fragments)
    mma_qk_kernel<<<dim3(NC / 64, NM / 128, 2), 256>>>(bq, bk, bo, nullptr, 0, 0);
    // 3) ARM 2: V via tf32 mma (on-the-fly split, raw fp32 inputs)
    tf32_v_kernel<<<dim3(NC / 64, NM / 128), 256>>>(x, Wv, bv);
    // 4) device-side verification of each arm
    ref_check_kernel<<<64, 256>>>(x, Wq, bq, 0);
    ref_check_kernel<<<64, 256>>>(x, Wv, bv, 1);
    // 5) fp32 fallback QKV (per-matrix gated; no-op for verified arms)
    sgemm_bias_kernel<<<dim3(NC / GBN, NM / GBM, 3), 256>>>(
        x, Wq, Wk, Wv, bq, bk, bv, nullptr, 0);
    // 6) attention
    flash_kernel<<<dim3(NT / FBQ, NB * NH), 128>>>();
    // 7) Y split (runs only if bf16 arm verified)
    convert_split_kernel<<<(NM * NC) / 1024, 256>>>(g_Y, g_Ahi, g_Alo, 1);
    // 8) out-proj: bf16 arm (gated) or fp32 fallback (inverse gate)
    mma_qk_kernel<<<dim3(NC / 64, NM / 128, 1), 256>>>(bq, bk, bo, out, 1, 1);
    sgemm_bias_kernel<<<dim3(NC / GBN, NM / GBM, 1), 256>>>(
        x, Wo, nullptr, nullptr, bo, nullptr, nullptr, out, 1);
}

// round 9
// speedup vs baseline: 1.1973x; 1.1973x over previous
#include <cuda_runtime.h>
#include <cuda_bf16.h>
#include <cstdint>
#include <math.h>

#define NB 2
#define NT 2048
#define NC 1024
#define NH 16
#define DH 64
#define NM (NB*NT)   // 4096 rows

// ---------------------------------------------------------------------------
// Scratch (__device__ globals; no allocations). NOTE: zero-initialized.
// ---------------------------------------------------------------------------
__device__ float g_Q[(size_t)NM*NC];
__device__ float g_K[(size_t)NM*NC];
__device__ float g_V[(size_t)NM*NC];
__device__ float g_Y[(size_t)NM*NC];
__device__ unsigned short g_Ahi[(size_t)NM*NC];          // bf16 raw
__device__ unsigned short g_Alo[(size_t)NM*NC];
__device__ unsigned short g_Wthi[(size_t)4*NC*NC];       // W^T [N,K] bf16 hi
__device__ unsigned short g_Wtlo[(size_t)4*NC*NC];       // W^T [N,K] bf16 lo
__device__ int g_badQ;   // bf16 staged arm failed verification

// ---------------------------------------------------------------------------
// Helpers
// ---------------------------------------------------------------------------
__device__ __forceinline__ uint32_t smem_u32(const void* p) {
    uint32_t a;
    asm("{ .reg .u64 t; cvta.to.shared.u64 t, %1; cvt.u32.u64 %0, t; }"
        : "=r"(a) : "l"(p));
    return a;
}
__device__ __forceinline__ uint32_t lds32(uint32_t a) {
    uint32_t r;
    asm volatile("ld.shared.b32 %0, [%1];" : "=r"(r) : "r"(a));
    return r;
}
__device__ __forceinline__ void sts128(uint32_t a, uint4 v) {
    asm volatile("st.shared.v4.b32 [%0], {%1,%2,%3,%4};"
        :: "r"(a), "r"(v.x), "r"(v.y), "r"(v.z), "r"(v.w));
}
__device__ __forceinline__ void mma_bf16(float* d, const uint32_t* a, const uint32_t* b) {
    asm volatile("mma.sync.aligned.m16n8k16.row.col.f32.bf16.bf16.f32 "
        "{%0,%1,%2,%3}, {%4,%5,%6,%7}, {%8,%9}, {%0,%1,%2,%3};"
        : "+f"(d[0]), "+f"(d[1]), "+f"(d[2]), "+f"(d[3])
        : "r"(a[0]), "r"(a[1]), "r"(a[2]), "r"(a[3]), "r"(b[0]), "r"(b[1]));
}
__device__ __forceinline__ void bsplit(float x, unsigned short& h, unsigned short& l) {
    __nv_bfloat16 bh = __float2bfloat16(x);
    float fh = __bfloat162float(bh);
    __nv_bfloat16 bl = __float2bfloat16(x - fh);
    h = __bfloat16_as_ushort(bh);
    l = __bfloat16_as_ushort(bl);
}

// ---------------------------------------------------------------------------
__global__ void zero_flag_kernel() { g_badQ = 0; }

// ---------------------------------------------------------------------------
// fp32 -> (hi, lo) bf16 split. gated=1: run only if staged arm verified.
// ---------------------------------------------------------------------------
__global__ __launch_bounds__(256)
void convert_split_kernel(const float* __restrict__ in,
                          unsigned short* __restrict__ hi,
                          unsigned short* __restrict__ lo, int gated)
{
    if (gated && g_badQ != 0) return;
    int i = blockIdx.x * blockDim.x + threadIdx.x;
    float4 v = ((const float4*)in)[i];
    ushort4 h, l;
    bsplit(v.x, h.x, l.x);
    bsplit(v.y, h.y, l.y);
    bsplit(v.z, h.z, l.z);
    bsplit(v.w, h.w, l.w);
    ((ushort4*)hi)[i] = h;
    ((ushort4*)lo)[i] = l;
}

// ---------------------------------------------------------------------------
// Weight transpose + split: W[K,N] fp32 -> Wt_hi/lo[N,K] bf16 (z = 0..3)
// ---------------------------------------------------------------------------
__global__ __launch_bounds__(256)
void wsplit_kernel(const float* __restrict__ Wq, const float* __restrict__ Wk,
                   const float* __restrict__ Wv, const float* __restrict__ Wo)
{
    __shared__ float t[32][33];
    int z = blockIdx.z;
    const float* W = (z == 0) ? Wq : (z == 1) ? Wk : (z == 2) ? Wv : Wo;
    int n0 = blockIdx.x * 32, k0 = blockIdx.y * 32;
    int tx = threadIdx.x, ty = threadIdx.y;
#pragma unroll
    for (int j = 0; j < 4; j++)
        t[ty + j * 8][tx] = W[(size_t)(k0 + ty + j * 8) * NC + n0 + tx];
    __syncthreads();
#pragma unroll
    for (int j = 0; j < 4; j++) {
        int r = ty + j * 8;
        float v = t[tx][r];
        size_t off = (size_t)z * NC * NC + (size_t)(n0 + r) * NC + k0 + tx;
        bsplit(v, g_Wthi[off], g_Wtlo[off]);
    }
}

// ---------------------------------------------------------------------------
// Staged bf16 mma GEMM: C[128x128 tile] = A @ Wt^T + bias, 3-term split.
// 256 thr, 8 warps (warp tile 32x64), K-chunk 16.
// Staging: plain uint4 LDG -> register prefetch -> STS.128. NO cp.async.
// Smem: uint4 array (16B-aligned by type), pitch 48 B for all 4 tiles ->
// fragment LDS rows (r*12 words mod 32) conflict-free.
// mode 0: z = blockIdx.z in {0,1,2} -> g_Q/g_K/g_V;  mode 1: z=3 -> Cext.
// gate=1: run only if g_badQ == 0.
// ---------------------------------------------------------------------------
#define PITCHB 48
#define TILEB (128*PITCHB)               // 6144 B per tile
#define STAGEB (4*TILEB)                 // 24576 B: [Ah | Al | Bh | Bl]

__global__ __launch_bounds__(256)
void mma_gemm_kernel(const float* __restrict__ bq, const float* __restrict__ bk,
                     const float* __restrict__ bv, const float* __restrict__ bo,
                     float* __restrict__ Cext, int mode, int gate)
{
    if (gate && g_badQ != 0) return;

    __shared__ uint4 sm4[STAGEB / 16];   // 24576 B, 16B-aligned by type
    int tid = threadIdx.x;
    int warp = tid >> 5, lane = tid & 31;
    int wm = warp & 3, wn = warp >> 2;
    int n0 = blockIdx.x * 128, m0 = blockIdx.y * 128;
    int z = (mode == 0) ? blockIdx.z : 3;
    const float* bias = (mode == 0) ? ((z == 0) ? bq : (z == 1) ? bk : bv) : bo;
    float* C = (mode == 0) ? ((z == 0) ? g_Q : (z == 1) ? g_K : g_V) : Cext;

    const unsigned short* gT0 = g_Ahi + (size_t)m0 * NC;
    const unsigned short* gT1 = g_Alo + (size_t)m0 * NC;
    const unsigned short* gT2 = g_Wthi + (size_t)z * NC * NC + (size_t)n0 * NC;
    const unsigned short* gT3 = g_Wtlo + (size_t)z * NC * NC + (size_t)n0 * NC;

    uint32_t sbase = smem_u32(sm4);

    // copy mapping: thread t -> row = t>>1, 8 elems at (t&1)*8 of 16-elem row
    int crow = tid >> 1;
    int cseg = (tid & 1) * 8;                       // element offset
    size_t gro = (size_t)crow * NC + cseg;
    uint32_t swo = (uint32_t)(crow * PITCHB + cseg * 2);

    // Fragment base byte offsets (R8-verified scheme):
    // a0 = A[rowbase+g][2t..2t+1]; a1 = +8 rows; a2 = +16 B (+8 k); a3 = both
    // b0 = Bt[nbase+g][2t..2t+1]; b1 = +16 B
    int g8 = lane >> 2, t4 = lane & 3;
    uint32_t aby = (uint32_t)((wm * 32 + g8) * PITCHB + t4 * 4);
    uint32_t bby = (uint32_t)((wn * 64 + g8) * PITCHB + t4 * 4);

    float acc[2][8][4];
#pragma unroll
    for (int mf = 0; mf < 2; mf++)
#pragma unroll
        for (int nf = 0; nf < 8; nf++)
#pragma unroll
            for (int q = 0; q < 4; q++) acc[mf][nf][q] = 0.0f;

    // prefetch chunk 0
    uint4 pA0 = *(const uint4*)(gT0 + gro);
    uint4 pA1 = *(const uint4*)(gT1 + gro);
    uint4 pB0 = *(const uint4*)(gT2 + gro);
    uint4 pB1 = *(const uint4*)(gT3 + gro);

    for (int i = 0; i < 64; i++) {
        __syncthreads();                 // previous compute done
        sts128(sbase + swo,             pA0);
        sts128(sbase + TILEB + swo,     pA1);
        sts128(sbase + 2 * TILEB + swo, pB0);
        sts128(sbase + 3 * TILEB + swo, pB1);
        __syncthreads();                 // tiles visible

        if (i + 1 < 64) {                // prefetch next chunk (overlaps mma)
            size_t go = gro + (size_t)(i + 1) * 16;
            pA0 = *(const uint4*)(gT0 + go);
            pA1 = *(const uint4*)(gT1 + go);
            pB0 = *(const uint4*)(gT2 + go);
            pB1 = *(const uint4*)(gT3 + go);
        }

        uint32_t afh[2][4], afl[2][4];
#pragma unroll
        for (int mf = 0; mf < 2; mf++) {
            uint32_t ab = sbase + aby + mf * (16 * PITCHB);
            afh[mf][0] = lds32(ab);
            afh[mf][1] = lds32(ab + 8 * PITCHB);
            afh[mf][2] = lds32(ab + 16);
            afh[mf][3] = lds32(ab + 8 * PITCHB + 16);
            uint32_t al = ab + TILEB;
            afl[mf][0] = lds32(al);
            afl[mf][1] = lds32(al + 8 * PITCHB);
            afl[mf][2] = lds32(al + 16);
            afl[mf][3] = lds32(al + 8 * PITCHB + 16);
        }
#pragma unroll
        for (int nf = 0; nf < 8; nf++) {
            uint32_t bb = sbase + 2 * TILEB + bby + nf * (8 * PITCHB);
            uint32_t bh[2], bl[2];
            bh[0] = lds32(bb);
            bh[1] = lds32(bb + 16);
            bl[0] = lds32(bb + TILEB);
            bl[1] = lds32(bb + TILEB + 16);
#pragma unroll
            for (int mf = 0; mf < 2; mf++) {
                mma_bf16(acc[mf][nf], afh[mf], bh);
                mma_bf16(acc[mf][nf], afl[mf], bh);
                mma_bf16(acc[mf][nf], afh[mf], bl);
            }
        }
    }

    // Epilogue (R8-verified c-fragment map)
#pragma unroll
    for (int mf = 0; mf < 2; mf++) {
        int r0 = m0 + wm * 32 + mf * 16 + g8;
#pragma unroll
        for (int nf = 0; nf < 8; nf++) {
            int col = n0 + wn * 64 + nf * 8 + t4 * 2;
            float2 b2 = *(const float2*)(bias + col);
            float2 o;
            o.x = acc[mf][nf][0] + b2.x; o.y = acc[mf][nf][1] + b2.y;
            *(float2*)(C + (size_t)r0 * NC + col) = o;
            o.x = acc[mf][nf][2] + b2.x; o.y = acc[mf][nf][3] + b2.y;
            *(float2*)(C + (size_t)(r0 + 8) * NC + col) = o;
        }
    }
}

// ---------------------------------------------------------------------------
// Device-side check: recompute Q[0:32, 0:128] in fp32 vs g_Q.
// ---------------------------------------------------------------------------
__global__ __launch_bounds__(256)
void ref_check_kernel(const float* __restrict__ x, const float* __restrict__ Wq,
                      const float* __restrict__ bq)
{
    int idx = blockIdx.x * 256 + threadIdx.x;   // 0..4095
    int r = idx >> 7, c = idx & 127;
    const float* xr = x + (size_t)r * NC;
    float s = 0.0f;
#pragma unroll 4
    for (int k = 0; k < NC; k++)
        s += xr[k] * Wq[(size_t)k * NC + c];
    s += bq[c];
    float q = g_Q[(size_t)r * NC + c];
    if (fabsf(q - s) > 0.02f * (fabsf(s) + 0.5f))
        atomicExch(&g_badQ, 1);
}

// ---------------------------------------------------------------------------
// Proven fp32 SGEMM fallback (runs only when g_badQ != 0).
// ---------------------------------------------------------------------------
#define GBM 128
#define GBN 128
#define GBK 8

__global__ __launch_bounds__(256)
void sgemm_bias_kernel(const float* __restrict__ Aext,
                       const float* __restrict__ W0, const float* __restrict__ W1,
                       const float* __restrict__ W2,
                       const float* __restrict__ b0, const float* __restrict__ b1,
                       const float* __restrict__ b2,
                       float* __restrict__ Cext, int mode)
{
    if (g_badQ == 0) return;

    const int N = NC, K = NC;
    const float* A; const float* W; const float* bias; float* C;
    int z = blockIdx.z;
    if (mode == 0) {
        A = Aext;
        W    = (z == 0) ? W0 : (z == 1) ? W1 : W2;
        bias = (z == 0) ? b0 : (z == 1) ? b1 : b2;
        C    = (z == 0) ? g_Q : (z == 1) ? g_K : g_V;
    } else {
        A = g_Y; W = W0; bias = b0; C = Cext;
    }

    __shared__ float As[GBK][GBM];
    __shared__ float Bs[GBK][GBN];

    int tid = threadIdx.x;
    int bx = blockIdx.x, by = blockIdx.y;

    float acc[8][8];
#pragma unroll
    for (int i = 0; i < 8; i++)
#pragma unroll
        for (int j = 0; j < 8; j++) acc[i][j] = 0.0f;

    const float* Ab = A + (size_t)by * GBM * K;
    const float* Wb = W + (size_t)bx * GBN;

    int arow = tid >> 1, acol = (tid & 1) * 4;
    int brow = tid >> 5, bcol = (tid & 31) * 4;
    int rg = (tid >> 4) * 8;
    int cg = (tid & 15) * 8;

    for (int kt = 0; kt < K; kt += GBK) {
        float4 av = *(const float4*)(Ab + (size_t)arow * K + kt + acol);
        float4 bv = *(const float4*)(Wb + (size_t)(kt + brow) * N + bcol);
        __syncthreads();
        As[acol + 0][arow] = av.x;
        As[acol + 1][arow] = av.y;
        As[acol + 2][arow] = av.z;
        As[acol + 3][arow] = av.w;
        *(float4*)&Bs[brow][bcol] = bv;
        __syncthreads();
#pragma unroll
        for (int k = 0; k < GBK; k++) {
            float ra[8], rb[8];
            *(float4*)&ra[0] = *(const float4*)&As[k][rg];
            *(float4*)&ra[4] = *(const float4*)&As[k][rg + 4];
            *(float4*)&rb[0] = *(const float4*)&Bs[k][cg];
            *(float4*)&rb[4] = *(const float4*)&Bs[k][cg + 4];
#pragma unroll
            for (int i = 0; i < 8; i++)
#pragma unroll
                for (int j = 0; j < 8; j++)
                    acc[i][j] += ra[i] * rb[j];
        }
    }

    size_t row0 = (size_t)by * GBM + rg;
    int col0 = bx * GBN + cg;
#pragma unroll
    for (int i = 0; i < 8; i++) {
#pragma unroll
        for (int j = 0; j < 8; j += 4) {
            float4 o;
            o.x = acc[i][j + 0] + bias[col0 + j + 0];
            o.y = acc[i][j + 1] + bias[col0 + j + 1];
            o.z = acc[i][j + 2] + bias[col0 + j + 2];
            o.w = acc[i][j + 3] + bias[col0 + j + 3];
            *(float4*)(C + (row0 + i) * N + col0 + j) = o;
        }
    }
}

// ---------------------------------------------------------------------------
// Flash attention (proven R1 version)
// ---------------------------------------------------------------------------
#define FBQ 64
#define FBK 32
#define QP 65
#define KP 66
#define SP 33

__global__ __launch_bounds__(128)
void flash_kernel()
{
    __shared__ float Qs[FBQ][QP];
    __shared__ float KS[2112];
    __shared__ float Vs[FBK][DH];

    int tid = threadIdx.x;
    int qt = blockIdx.x;
    int bh = blockIdx.y;
    int b = bh >> 4, h = bh & 15;

    const float* Qg = g_Q + (size_t)b * NT * NC + h * DH;
    const float* Kg = g_K + (size_t)b * NT * NC + h * DH;
    const float* Vg = g_V + (size_t)b * NT * NC + h * DH;

    int ty = tid >> 3;
    int tx = tid & 7;
    int ty4 = ty * 4;

    {
        int lq = tid >> 4;
        int d  = (tid & 15) * 4;
#pragma unroll
        for (int r = 0; r < 8; r++) {
            int q = lq + r * 8;
            float4 v = *(const float4*)(Qg + (size_t)(qt * FBQ + q) * NC + d);
            Qs[q][d + 0] = v.x * 0.125f;
            Qs[q][d + 1] = v.y * 0.125f;
            Qs[q][d + 2] = v.z * 0.125f;
            Qs[q][d + 3] = v.w * 0.125f;
        }
    }

    float oa[4][8];
    float m_r[4], l_r[4];
#pragma unroll
    for (int i = 0; i < 4; i++) {
        m_r[i] = -1e30f; l_r[i] = 0.0f;
#pragma unroll
        for (int c = 0; c < 8; c++) oa[i][c] = 0.0f;
    }

    for (int kt = 0; kt < NT / FBK; kt++) {
        const float* Kt = Kg + (size_t)(kt * FBK) * NC;
        const float* Vt = Vg + (size_t)(kt * FBK) * NC;

        __syncthreads();
        {
            int lk = tid >> 4;
            int d  = (tid & 15) * 4;
#pragma unroll
            for (int r = 0; r < 4; r++) {
                int key = lk + r * 8;
                float4 kv = *(const float4*)(Kt + (size_t)key * NC + d);
                float* Kp = &KS[key * KP + d];
                Kp[0] = kv.x; Kp[1] = kv.y; Kp[2] = kv.z; Kp[3] = kv.w;
                float4 vv = *(const float4*)(Vt + (size_t)key * NC + d);
                *(float4*)&Vs[key][d] = vv;
            }
        }
        __syncthreads();

        float s[4][4];
#pragma unroll
        for (int i = 0; i < 4; i++)
#pragma unroll
            for (int j = 0; j < 4; j++) s[i][j] = 0.0f;

#pragma unroll 4
        for (int d = 0; d < DH; d++) {
            float rq[4], rk[4];
#pragma unroll
            for (int i = 0; i < 4; i++) rq[i] = Qs[ty4 + i][d];
#pragma unroll
            for (int j = 0; j < 4; j++) rk[j] = KS[(tx + 8 * j) * KP + d];
#pragma unroll
            for (int i = 0; i < 4; i++)
#pragma unroll
                for (int j = 0; j < 4; j++)
                    s[i][j] += rq[i] * rk[j];
        }
        __syncthreads();

        float p[4][4], corr[4], rsum[4];
#pragma unroll
        for (int i = 0; i < 4; i++) {
            float tm = fmaxf(fmaxf(s[i][0], s[i][1]), fmaxf(s[i][2], s[i][3]));
            tm = fmaxf(tm, __shfl_xor_sync(0xffffffffu, tm, 1));
            tm = fmaxf(tm, __shfl_xor_sync(0xffffffffu, tm, 2));
            tm = fmaxf(tm, __shfl_xor_sync(0xffffffffu, tm, 4));
            float mnew = fmaxf(m_r[i], tm);
            corr[i] = __expf(m_r[i] - mnew);
            float rs = 0.0f;
#pragma unroll
            for (int j = 0; j < 4; j++) {
                p[i][j] = __expf(s[i][j] - mnew);
                rs += p[i][j];
            }
            rs += __shfl_xor_sync(0xffffffffu, rs, 1);
            rs += __shfl_xor_sync(0xffffffffu, rs, 2);
            rs += __shfl_xor_sync(0xffffffffu, rs, 4);
            rsum[i] = rs;
            m_r[i] = mnew;
        }
#pragma unroll
        for (int i = 0; i < 4; i++) {
            l_r[i] = l_r[i] * corr[i] + rsum[i];
#pragma unroll
            for (int c = 0; c < 8; c++) oa[i][c] *= corr[i];
        }

#pragma unroll
        for (int i = 0; i < 4; i++)
#pragma unroll
            for (int j = 0; j < 4; j++)
                KS[(ty4 + i) * SP + (tx + 8 * j)] = p[i][j];
        __syncthreads();

#pragma unroll 4
        for (int k = 0; k < FBK; k++) {
            float rs[4];
#pragma unroll
            for (int i = 0; i < 4; i++) rs[i] = KS[(ty4 + i) * SP + k];
            float4 v0 = *(const float4*)&Vs[k][tx * 8];
            float4 v1 = *(const float4*)&Vs[k][tx * 8 + 4];
#pragma unroll
            for (int i = 0; i < 4; i++) {
                oa[i][0] += rs[i] * v0.x;
                oa[i][1] += rs[i] * v0.y;
                oa[i][2] += rs[i] * v0.z;
                oa[i][3] += rs[i] * v0.w;
                oa[i][4] += rs[i] * v1.x;
                oa[i][5] += rs[i] * v1.y;
                oa[i][6] += rs[i] * v1.z;
                oa[i][7] += rs[i] * v1.w;
            }
        }
    }

#pragma unroll
    for (int i = 0; i < 4; i++) {
        float inv = 1.0f / l_r[i];
        size_t row = (size_t)b * NT + qt * FBQ + ty4 + i;
        float* Yp = g_Y + row * NC + h * DH + tx * 8;
        float4 o0, o1;
        o0.x = oa[i][0] * inv; o0.y = oa[i][1] * inv;
        o0.z = oa[i][2] * inv; o0.w = oa[i][3] * inv;
        o1.x = oa[i][4] * inv; o1.y = oa[i][5] * inv;
        o1.z = oa[i][6] * inv; o1.w = oa[i][7] * inv;
        *(float4*)Yp = o0;
        *(float4*)(Yp + 4) = o1;
    }
}

// ---------------------------------------------------------------------------
extern "C" void kernel_launch(void* const* d_in, const int* in_sizes, int n_in,
                              void* d_out, int out_size)
{
    const float* x  = (const float*)d_in[0];
    const float* Wq = (const float*)d_in[1];
    const float* bq = (const float*)d_in[2];
    const float* Wk = (const float*)d_in[3];
    const float* bk = (const float*)d_in[4];
    const float* Wv = (const float*)d_in[5];
    const float* bv = (const float*)d_in[6];
    const float* Wo = (const float*)d_in[7];
    const float* bo = (const float*)d_in[8];
    float* out = (float*)d_out;

    // 0) reset flag
    zero_flag_kernel<<<1, 1>>>();
    // 1) bf16 splits (x + all weights)
    convert_split_kernel<<<(NM * NC) / 1024, 256>>>(x, g_Ahi, g_Alo, 0);
    wsplit_kernel<<<dim3(NC / 32, NC / 32, 4), dim3(32, 8)>>>(Wq, Wk, Wv, Wo);
    // 2) staged bf16 QKV (STS staging, no cp.async)
    mma_gemm_kernel<<<dim3(NC / 128, NM / 128, 3), 256>>>(
        bq, bk, bv, bo, nullptr, 0, 0);
    // 3) device-side verification (Q tile)
    ref_check_kernel<<<16, 256>>>(x, Wq, bq);
    // 4) fp32 fallback QKV (no-op when verified)
    sgemm_bias_kernel<<<dim3(NC / GBN, NM / GBM, 3), 256>>>(
        x, Wq, Wk, Wv, bq, bk, bv, nullptr, 0);
    // 5) attention
    flash_kernel<<<dim3(NT / FBQ, NB * NH), 128>>>();
    // 6) Y split (gated)
    convert_split_kernel<<<(NM * NC) / 1024, 256>>>(g_Y, g_Ahi, g_Alo, 1);
    // 7) out-proj: staged bf16 (gated) / fp32 fallback (inverse gate)
    mma_gemm_kernel<<<dim3(NC / 128, NM / 128, 1), 256>>>(
        bq, bk, bv, bo, out, 1, 1);
    sgemm_bias_kernel<<<dim3(NC / GBN, NM / GBM, 1), 256>>>(
        x, Wo, nullptr, nullptr, bo, nullptr, nullptr, out, 1);
}